// round 15
// baseline (speedup 1.0000x reference)
#include <cuda_runtime.h>
#include <cuda_fp16.h>
#include <cstdint>

// Problem constants
#define BB 8
#define SS 8192
#define KK 256            // IN
#define HH 256            // H
#define MT (BB * SS)      // 65536 rows
#define LC2 64            // apply-chunk length
#define CC2 (SS / LC2)    // 128 half-chunks per batch

// Tiled operand layouts (16KB tiles, SW128-preswizzled [128 rows][64 k] fp16)
// g_xh: [512 mblk][4 kc][8192 fp16]
// g_wh: [4 chblk][4 kc][8192 fp16]  (row j = logical col, W-row-permuted)
__device__ __half2 g_cv[MT * HH];               // 64 MB: packed (c, v) per (row, ch)
__device__ float g_At[BB * HH * CC2];           // transposed: [b][h][chunk]
__device__ float g_Bt[BB * HH * CC2];
__device__ float g_P[BB * CC2 * HH];            // [b][chunk][h]
__device__ __half g_xh[MT * KK];                // 32 MB
__device__ __half g_wh[2 * HH * KK];

// ---------------------------------------------------------------------------
// Portable PTX helpers (base ISA; no 'a'-suffix features)
// ---------------------------------------------------------------------------
__device__ __forceinline__ uint32_t smem_u32(const void* p) {
    uint32_t a;
    asm("{ .reg .u64 t; cvta.to.shared.u64 t, %1; cvt.u32.u64 %0, t; }" : "=r"(a) : "l"(p));
    return a;
}
__device__ __forceinline__ float frcp(float x) {
    float r;
    asm("rcp.approx.f32 %0, %1;" : "=f"(r) : "f"(x));
    return r;
}
__device__ __forceinline__ void ldsm4(uint32_t& r0, uint32_t& r1, uint32_t& r2, uint32_t& r3,
                                      uint32_t addr) {
    asm volatile("ldmatrix.sync.aligned.m8n8.x4.shared.b16 {%0,%1,%2,%3}, [%4];"
                 : "=r"(r0), "=r"(r1), "=r"(r2), "=r"(r3) : "r"(addr));
}
__device__ __forceinline__ void mma16816(float* d, const uint32_t* a, uint32_t b0, uint32_t b1) {
    asm volatile(
        "mma.sync.aligned.m16n8k16.row.col.f32.f16.f16.f32 "
        "{%0,%1,%2,%3}, {%4,%5,%6,%7}, {%8,%9}, {%0,%1,%2,%3};"
        : "+f"(d[0]), "+f"(d[1]), "+f"(d[2]), "+f"(d[3])
        : "r"(a[0]), "r"(a[1]), "r"(a[2]), "r"(a[3]), "r"(b0), "r"(b1));
}
__device__ __forceinline__ void mbar_init(uint32_t addr, uint32_t cnt) {
    asm volatile("mbarrier.init.shared.b64 [%0], %1;" :: "r"(addr), "r"(cnt) : "memory");
}
__device__ __forceinline__ void mbar_expect_tx(uint32_t addr, uint32_t bytes) {
    asm volatile("mbarrier.arrive.expect_tx.shared.b64 _, [%0], %1;"
                 :: "r"(addr), "r"(bytes) : "memory");
}
__device__ __forceinline__ void mbar_wait(uint32_t addr, uint32_t parity) {
    asm volatile(
        "{\n\t.reg .pred P1;\n\t"
        "WL_%=:\n\t"
        "mbarrier.try_wait.parity.acquire.cta.shared::cta.b64 P1, [%0], %1, 0x989680;\n\t"
        "@P1 bra.uni WD_%=;\n\t"
        "bra.uni WL_%=;\n\t"
        "WD_%=:\n\t}"
        :: "r"(addr), "r"(parity) : "memory");
}
__device__ __forceinline__ void bulk_g2s(uint32_t dst, const void* src, uint32_t bytes,
                                         uint32_t mbar) {
    asm volatile(
        "cp.async.bulk.shared::cta.global.mbarrier::complete_tx::bytes [%0], [%1], %2, [%3];"
        :: "r"(dst), "l"(src), "r"(bytes), "r"(mbar) : "memory");
}

#define SW128(o) ((o) ^ (((o) >> 3) & 0x70))

// ---------------------------------------------------------------------------
// Kernel D: no-op launch-slot shim (keeps the GEMM in ncu's capture slot).
// ---------------------------------------------------------------------------
__global__ void slot_kernel() {}

// ---------------------------------------------------------------------------
// Kernel 0a: x -> pre-swizzled tiled fp16. One thread per 16B unit.
// ---------------------------------------------------------------------------
__global__ __launch_bounds__(256)
void split_x_kernel(const float* __restrict__ in)
{
    const int total = MT * 32;                 // 16B units (32 per row)
    int u = blockIdx.x * blockDim.x + threadIdx.x;
    const int stride = gridDim.x * blockDim.x;
    char* hi_b = (char*)g_xh;
    for (; u < total; u += stride) {
        const int m = u >> 5;
        const int kg = u & 31;
        const int kc = kg >> 3, sk = kg & 7;
        const int mblk = m >> 7, mr = m & 127;
        const float* src = in + (size_t)m * KK + kg * 8;
        float4 v0 = *(const float4*)src;
        float4 v1 = *(const float4*)(src + 4);
        __half h[8];
        float f[8] = {v0.x, v0.y, v0.z, v0.w, v1.x, v1.y, v1.z, v1.w};
#pragma unroll
        for (int e = 0; e < 8; ++e) h[e] = __float2half_rn(f[e]);
        const size_t off = (size_t)(mblk * 4 + kc) * 16384 + SW128(mr * 128 + sk * 16);
        *(uint4*)(hi_b + off) = *(uint4*)h;
    }
}

// ---------------------------------------------------------------------------
// Kernel 0b: W -> pre-swizzled tiled fp16 with gate/hidden interleave:
// tile row j <- W row (ch | part<<8), j = 2*(ch&63) + part, chblk = ch>>6.
// ---------------------------------------------------------------------------
__global__ __launch_bounds__(256)
void split_w_kernel(const float* __restrict__ in)
{
    const int total = 512 * 32;                // W rows x 16B units
    int u = blockIdx.x * blockDim.x + threadIdx.x;
    if (u >= total) return;
    const int wrow = u >> 5;
    const int kg = u & 31;
    const int kc = kg >> 3, sk = kg & 7;
    const int part = wrow >> 8;                // 0=gate, 1=hidden
    const int ch = wrow & 255;
    const int chblk = ch >> 6;
    const int j = 2 * (ch & 63) + part;
    const float* src = in + (size_t)wrow * KK + kg * 8;
    float4 v0 = *(const float4*)src;
    float4 v1 = *(const float4*)(src + 4);
    __half h[8];
    float f[8] = {v0.x, v0.y, v0.z, v0.w, v1.x, v1.y, v1.z, v1.w};
#pragma unroll
    for (int e = 0; e < 8; ++e) h[e] = __float2half_rn(f[e]);
    const size_t off = (size_t)(chblk * 4 + kc) * 16384 + SW128(j * 128 + sk * 16);
    *(uint4*)((char*)g_wh + off) = *(uint4*)h;
}

// ---------------------------------------------------------------------------
// Kernel 1: fp16 GEMM via mma.sync + branchless fused gate epilogue
// (packed half2 c/v) + fused half-chunk scan aggregates. Grid (4, 512).
// CTA: 128 rows x 64 channels. 4 K-chunks of 64, 3 stages, barrier-light.
// LDSM addresses: SW128(R*128 + inner) == R*128 + (inner ^ ((R&7)<<4)) with
// R&7 == lrow&7 for all fragments -> swizzle hoisted out of the mainloop,
// every ldsm address is a single ADD.
// ---------------------------------------------------------------------------
#define STAGE_BYTES 32768
#define MBAR_OFF (3 * STAGE_BYTES)
#define SMEM_TOTAL_GEMM (3 * STAGE_BYTES + 64)
#define NCHUNK 4
#define CVP 66               // padded half2 row stride for epilogue smem

__global__ __launch_bounds__(256, 2)
void gemm_mma_kernel(const float* __restrict__ bias)
{
    extern __shared__ char smem[];
    const uint32_t sbase = smem_u32(smem);
    const int tid = threadIdx.x;
    const int wid = tid >> 5;
    const int lane = tid & 31;
    const int warpM = wid & 3;
    const int warpN = wid >> 2;
    const int mblk = blockIdx.y;
    const int chblk = blockIdx.x;
    const int mBase = mblk * 128;
    const int chBase = chblk * 64;

    if (tid == 0) {
#pragma unroll
        for (int s = 0; s < 3; ++s) mbar_init(sbase + MBAR_OFF + s * 8, 1);
    }
    __syncthreads();

    auto issue = [&](int i, int s) {
        if (tid == 0) {
            const int kc = i & 3;
            const uint32_t mb = sbase + MBAR_OFF + s * 8;
            mbar_expect_tx(mb, STAGE_BYTES);
            bulk_g2s(sbase + s * STAGE_BYTES,
                     g_xh + (size_t)(mblk * 4 + kc) * 8192, 16384, mb);
            bulk_g2s(sbase + s * STAGE_BYTES + 16384,
                     g_wh + (size_t)(chblk * 4 + kc) * 8192, 16384, mb);
        }
    };

    // Prefetch chunks 0,1,2 into stages 0,1,2
    issue(0, 0);
    issue(1, 1);
    issue(2, 2);

    float acc[2][8][4];
#pragma unroll
    for (int mt = 0; mt < 2; ++mt)
#pragma unroll
        for (int nt = 0; nt < 8; ++nt)
#pragma unroll
            for (int e = 0; e < 4; ++e) acc[mt][nt][e] = 0.f;

    const int lrow = lane & 15;
    const int lkg = lane >> 4;

    // Hoisted swizzle: per-thread swizzled inner offsets and row byte-bases.
    const uint32_t xorpat = (uint32_t)(lrow & 7) << 4;
    uint32_t innerx[4];
#pragma unroll
    for (int ks = 0; ks < 4; ++ks)
        innerx[ks] = ((uint32_t)(ks * 32 + lkg * 16)) ^ xorpat;
    uint32_t aRow[2], bRow[4];
#pragma unroll
    for (int mt = 0; mt < 2; ++mt)
        aRow[mt] = (uint32_t)(warpM * 32 + mt * 16 + lrow) * 128;
#pragma unroll
    for (int ng = 0; ng < 4; ++ng)
        bRow[ng] = (uint32_t)(warpN * 64 + ng * 16 + lrow) * 128;

    auto compute_chunk = [&](uint32_t sA) {
        const uint32_t sB = sA + 16384;
#pragma unroll
        for (int ks = 0; ks < 4; ++ks) {
            const uint32_t ix = innerx[ks];
            uint32_t a[2][4];
#pragma unroll
            for (int mt = 0; mt < 2; ++mt)
                ldsm4(a[mt][0], a[mt][1], a[mt][2], a[mt][3], sA + aRow[mt] + ix);
            uint32_t bf[4][4];
#pragma unroll
            for (int ng = 0; ng < 4; ++ng)
                ldsm4(bf[ng][0], bf[ng][1], bf[ng][2], bf[ng][3], sB + bRow[ng] + ix);
#pragma unroll
            for (int mt = 0; mt < 2; ++mt)
#pragma unroll
                for (int ng = 0; ng < 4; ++ng) {
                    mma16816(acc[mt][2 * ng],     a[mt], bf[ng][0], bf[ng][2]);
                    mma16816(acc[mt][2 * ng + 1], a[mt], bf[ng][1], bf[ng][3]);
                }
        }
    };

    // Chunk 0 (stage 0, phase 0)
    mbar_wait(sbase + MBAR_OFF + 0, 0);
    compute_chunk(sbase);
    __syncthreads();                 // all warps drained stage 0
    issue(3, 0);                     // refill stage 0 with chunk 3

    // Chunks 1, 2 (stages 1, 2, phase 0) — no block syncs
    mbar_wait(sbase + MBAR_OFF + 8, 0);
    compute_chunk(sbase + STAGE_BYTES);
    mbar_wait(sbase + MBAR_OFF + 16, 0);
    compute_chunk(sbase + 2 * STAGE_BYTES);

    // Chunk 3 (stage 0, phase 1)
    mbar_wait(sbase + MBAR_OFF + 0, 1);
    compute_chunk(sbase);

    __syncthreads();   // all warps done with stage smem -> reuse for c/v tile

    // Branchless epilogue: gate math -> packed (c, v) half2 in smem.
    __half2* cv_sm = (__half2*)smem;       // [128][CVP]
    const int qrow = lane >> 2;
    const int qch = lane & 3;

#pragma unroll
    for (int nt = 0; nt < 8; ++nt) {
        const int chL = warpN * 32 + nt * 4 + qch;
        const float bg = __ldg(bias + chBase + chL);
        const float bh = __ldg(bias + 256 + chBase + chL);
#pragma unroll
        for (int mt = 0; mt < 2; ++mt) {
#pragma unroll
            for (int half = 0; half < 2; ++half) {
                const int r = warpM * 32 + mt * 16 + half * 8 + qrow;
                const float gate = acc[mt][nt][2 * half] + bg;
                const float hid  = acc[mt][nt][2 * half + 1] + bh;

                const float e1 = __expf(-fabsf(gate));
                const float i1 = frcp(1.f + e1);
                const float sp = i1;            // sigma(|gate|)
                const float sn = e1 * i1;       // sigma(-|gate|)
                const bool gpos = gate >= 0.f;
                const float z = gpos ? sp : sn; // sigma(gate)
                const float c = gpos ? sn : sp; // sigma(-gate)

                const float e2 = __expf(-fabsf(hid));
                const float i2 = frcp(1.f + e2);
                const float sgh = e2 * i2;      // sigma(hid) for hid<0
                const float gv = (hid >= 0.f) ? (hid + 0.5f) : sgh;

                cv_sm[r * CVP + chL] = __floats2half2_rn(c, z * gv);
            }
        }
    }
    __syncthreads();

    // Coalesced global stores of packed c/v
    for (int idx = tid; idx < 128 * 64; idx += 256) {
        int r = idx >> 6, ch = idx & 63;
        g_cv[(size_t)(mBase + r) * HH + chBase + ch] = cv_sm[r * CVP + ch];
    }

    // Fused half-chunk scan aggregates from the ROUNDED fp16 values
    // (consistent with what apply reads) -> transposed layout [b][h][chunk].
    if (tid < 128) {
        const int ch = tid & 63;
        const int hp = tid >> 6;
        float A = 1.f, Bv = 0.f;
        const int r0 = hp * 64;
#pragma unroll 8
        for (int r = 0; r < 64; ++r) {
            float2 cv = __half22float2(cv_sm[(r0 + r) * CVP + ch]);
            Bv = fmaf(cv.x, Bv, cv.y);
            A *= cv.x;
        }
        const int gchunk = blockIdx.y * 2 + hp;
        const int b = gchunk >> 7;
        const int lc = gchunk & 127;
        const int h = chBase + ch;
        size_t gi = ((size_t)b * HH + h) * CC2 + lc;
        g_At[gi] = A;
        g_Bt[gi] = Bv;
    }
}

// ---------------------------------------------------------------------------
// Kernel 2: warp-parallel combine. One warp per (b,h) chain of 128 chunks.
// ---------------------------------------------------------------------------
__global__ __launch_bounds__(256)
void scan_combine_kernel(const float* __restrict__ h0)
{
    const int wid = threadIdx.x >> 5;
    const int lane = threadIdx.x & 31;
    const int chain = blockIdx.x * 8 + wid;       // 0..2047
    const int b = chain >> 8;
    const int h = chain & 255;

    const size_t base = ((size_t)b * HH + h) * CC2 + lane * 4;
    float4 A4 = *(const float4*)(g_At + base);
    float4 B4 = *(const float4*)(g_Bt + base);

    float a = A4.x, bb = B4.x;
    a = A4.y * a;  bb = fmaf(A4.y, bb, B4.y);
    a = A4.z * a;  bb = fmaf(A4.z, bb, B4.z);
    a = A4.w * a;  bb = fmaf(A4.w, bb, B4.w);

    float sa = a, sb = bb;
#pragma unroll
    for (int d = 1; d < 32; d <<= 1) {
        float pa = __shfl_up_sync(0xFFFFFFFFu, sa, d);
        float pb = __shfl_up_sync(0xFFFFFFFFu, sb, d);
        if (lane >= d) {
            sb = fmaf(sa, pb, sb);
            sa = sa * pa;
        }
    }
    float ea = __shfl_up_sync(0xFFFFFFFFu, sa, 1);
    float eb = __shfl_up_sync(0xFFFFFFFFu, sb, 1);
    if (lane == 0) { ea = 1.f; eb = 0.f; }

    float P = fmaf(ea, h0[b * HH + h], eb);

    const int c0 = lane * 4;
    size_t pi = ((size_t)b * CC2 + c0) * HH + h;
    g_P[pi] = P;             P = fmaf(A4.x, P, B4.x);
    g_P[pi + HH] = P;        P = fmaf(A4.y, P, B4.y);
    g_P[pi + 2 * HH] = P;    P = fmaf(A4.z, P, B4.z);
    g_P[pi + 3 * HH] = P;
}

// ---------------------------------------------------------------------------
// Kernel 3: apply carry-in over 64-step half-chunks, write outputs + h_next
// ---------------------------------------------------------------------------
__global__ __launch_bounds__(256)
void scan_apply_kernel(float* __restrict__ out, int out_size)
{
    const int bk = blockIdx.x;
    const int h = threadIdx.x;
    const int b = bk / CC2;
    const int chunk = bk % CC2;
    float hc = g_P[bk * HH + h];
    const size_t base = (size_t)bk * LC2 * HH + h;
#pragma unroll 8
    for (int t = 0; t < LC2; ++t) {
        float2 cv = __half22float2(g_cv[base + (size_t)t * HH]);
        hc = fmaf(cv.x, hc, cv.y);
        out[base + (size_t)t * HH] = hc;
    }
    if (chunk == CC2 - 1) {
        const long long off = (long long)MT * HH + b * HH + h;
        if (off < (long long)out_size) out[off] = hc;
    }
}

// ---------------------------------------------------------------------------
extern "C" void kernel_launch(void* const* d_in, const int* in_sizes, int n_in,
                              void* d_out, int out_size)
{
    const float* x  = (const float*)d_in[0];   // (B, S, IN)
    const float* h0 = (const float*)d_in[1];   // (B, 1, H)
    const float* W  = (const float*)d_in[2];   // (2H, IN)
    const float* b  = (const float*)d_in[3];   // (2H,)
    float* out = (float*)d_out;

    cudaFuncSetAttribute(gemm_mma_kernel,
                         cudaFuncAttributeMaxDynamicSharedMemorySize, SMEM_TOTAL_GEMM);

    slot_kernel<<<1, 32>>>();                  // launch-slot shim (see Kernel D)
    split_x_kernel<<<1024, 256>>>(x);
    split_w_kernel<<<64, 256>>>(W);

    dim3 ggrid(4, 512);
    gemm_mma_kernel<<<ggrid, 256, SMEM_TOTAL_GEMM>>>(b);
    scan_combine_kernel<<<256, 256>>>(h0);
    scan_apply_kernel<<<BB * CC2, 256>>>(out, out_size);
}

// round 16
// speedup vs baseline: 1.0169x; 1.0169x over previous
#include <cuda_runtime.h>
#include <cuda_fp16.h>
#include <cstdint>

// Problem constants
#define BB 8
#define SS 8192
#define KK 256            // IN
#define HH 256            // H
#define MT (BB * SS)      // 65536 rows
#define LC2 64            // apply-chunk length
#define CC2 (SS / LC2)    // 128 half-chunks per batch

// Tiled operand layouts (16KB tiles, SW128-preswizzled [128 rows][64 k] fp16)
// g_xh: [512 mblk][4 kc][8192 fp16]
// g_wh: [4 chblk][4 kc][8192 fp16]  (row j = logical col, W-row-permuted)
__device__ __half2 g_cv[MT * HH];               // 64 MB: packed (c, v) per (row, ch)
__device__ float g_At[BB * HH * CC2];           // transposed: [b][h][chunk]
__device__ float g_Bt[BB * HH * CC2];
__device__ float g_P[BB * CC2 * HH];            // [b][chunk][h]
__device__ __half g_xh[MT * KK];                // 32 MB
__device__ __half g_wh[2 * HH * KK];

// ---------------------------------------------------------------------------
// Portable PTX helpers (base ISA; no 'a'-suffix features)
// ---------------------------------------------------------------------------
__device__ __forceinline__ uint32_t smem_u32(const void* p) {
    uint32_t a;
    asm("{ .reg .u64 t; cvta.to.shared.u64 t, %1; cvt.u32.u64 %0, t; }" : "=r"(a) : "l"(p));
    return a;
}
__device__ __forceinline__ float frcp(float x) {
    float r;
    asm("rcp.approx.f32 %0, %1;" : "=f"(r) : "f"(x));
    return r;
}
__device__ __forceinline__ void ldsm4(uint32_t& r0, uint32_t& r1, uint32_t& r2, uint32_t& r3,
                                      uint32_t addr) {
    asm volatile("ldmatrix.sync.aligned.m8n8.x4.shared.b16 {%0,%1,%2,%3}, [%4];"
                 : "=r"(r0), "=r"(r1), "=r"(r2), "=r"(r3) : "r"(addr));
}
__device__ __forceinline__ void mma16816(float* d, const uint32_t* a, uint32_t b0, uint32_t b1) {
    asm volatile(
        "mma.sync.aligned.m16n8k16.row.col.f32.f16.f16.f32 "
        "{%0,%1,%2,%3}, {%4,%5,%6,%7}, {%8,%9}, {%0,%1,%2,%3};"
        : "+f"(d[0]), "+f"(d[1]), "+f"(d[2]), "+f"(d[3])
        : "r"(a[0]), "r"(a[1]), "r"(a[2]), "r"(a[3]), "r"(b0), "r"(b1));
}
__device__ __forceinline__ void mbar_init(uint32_t addr, uint32_t cnt) {
    asm volatile("mbarrier.init.shared.b64 [%0], %1;" :: "r"(addr), "r"(cnt) : "memory");
}
__device__ __forceinline__ void mbar_expect_tx(uint32_t addr, uint32_t bytes) {
    asm volatile("mbarrier.arrive.expect_tx.shared.b64 _, [%0], %1;"
                 :: "r"(addr), "r"(bytes) : "memory");
}
__device__ __forceinline__ void mbar_wait(uint32_t addr, uint32_t parity) {
    asm volatile(
        "{\n\t.reg .pred P1;\n\t"
        "WL_%=:\n\t"
        "mbarrier.try_wait.parity.acquire.cta.shared::cta.b64 P1, [%0], %1, 0x989680;\n\t"
        "@P1 bra.uni WD_%=;\n\t"
        "bra.uni WL_%=;\n\t"
        "WD_%=:\n\t}"
        :: "r"(addr), "r"(parity) : "memory");
}
__device__ __forceinline__ void bulk_g2s(uint32_t dst, const void* src, uint32_t bytes,
                                         uint32_t mbar) {
    asm volatile(
        "cp.async.bulk.shared::cta.global.mbarrier::complete_tx::bytes [%0], [%1], %2, [%3];"
        :: "r"(dst), "l"(src), "r"(bytes), "r"(mbar) : "memory");
}

#define SW128(o) ((o) ^ (((o) >> 3) & 0x70))

// ---------------------------------------------------------------------------
// Kernel D: no-op launch-slot shim (keeps the GEMM in ncu's capture slot).
// ---------------------------------------------------------------------------
__global__ void slot_kernel() {}

// ---------------------------------------------------------------------------
// Kernel 0a: x -> pre-swizzled tiled fp16. One thread per 16B unit.
// ---------------------------------------------------------------------------
__global__ __launch_bounds__(256)
void split_x_kernel(const float* __restrict__ in)
{
    const int total = MT * 32;                 // 16B units (32 per row)
    int u = blockIdx.x * blockDim.x + threadIdx.x;
    const int stride = gridDim.x * blockDim.x;
    char* hi_b = (char*)g_xh;
    for (; u < total; u += stride) {
        const int m = u >> 5;
        const int kg = u & 31;
        const int kc = kg >> 3, sk = kg & 7;
        const int mblk = m >> 7, mr = m & 127;
        const float* src = in + (size_t)m * KK + kg * 8;
        float4 v0 = *(const float4*)src;
        float4 v1 = *(const float4*)(src + 4);
        __half h[8];
        float f[8] = {v0.x, v0.y, v0.z, v0.w, v1.x, v1.y, v1.z, v1.w};
#pragma unroll
        for (int e = 0; e < 8; ++e) h[e] = __float2half_rn(f[e]);
        const size_t off = (size_t)(mblk * 4 + kc) * 16384 + SW128(mr * 128 + sk * 16);
        *(uint4*)(hi_b + off) = *(uint4*)h;
    }
}

// ---------------------------------------------------------------------------
// Kernel 0b: W -> pre-swizzled tiled fp16 with gate/hidden interleave:
// tile row j <- W row (ch | part<<8), j = 2*(ch&63) + part, chblk = ch>>6.
// ---------------------------------------------------------------------------
__global__ __launch_bounds__(256)
void split_w_kernel(const float* __restrict__ in)
{
    const int total = 512 * 32;                // W rows x 16B units
    int u = blockIdx.x * blockDim.x + threadIdx.x;
    if (u >= total) return;
    const int wrow = u >> 5;
    const int kg = u & 31;
    const int kc = kg >> 3, sk = kg & 7;
    const int part = wrow >> 8;                // 0=gate, 1=hidden
    const int ch = wrow & 255;
    const int chblk = ch >> 6;
    const int j = 2 * (ch & 63) + part;
    const float* src = in + (size_t)wrow * KK + kg * 8;
    float4 v0 = *(const float4*)src;
    float4 v1 = *(const float4*)(src + 4);
    __half h[8];
    float f[8] = {v0.x, v0.y, v0.z, v0.w, v1.x, v1.y, v1.z, v1.w};
#pragma unroll
    for (int e = 0; e < 8; ++e) h[e] = __float2half_rn(f[e]);
    const size_t off = (size_t)(chblk * 4 + kc) * 16384 + SW128(j * 128 + sk * 16);
    *(uint4*)((char*)g_wh + off) = *(uint4*)h;
}

// ---------------------------------------------------------------------------
// Kernel 1: fp16 GEMM via mma.sync + predicate-light fused gate epilogue
// (packed half2 c/v) + all-thread fused scan aggregates. Grid (4, 512).
// CTA: 128 rows x 64 channels. 4 K-chunks of 64, 3 stages, barrier-light.
// ---------------------------------------------------------------------------
#define STAGE_BYTES 32768
#define MBAR_OFF (3 * STAGE_BYTES)
#define SMEM_TOTAL_GEMM (3 * STAGE_BYTES + 64)
#define NCHUNK 4
#define CVP 66               // padded half2 row stride for epilogue smem
#define PART_OFF 36864       // byte offset of partial-aggregate arrays in smem

__global__ __launch_bounds__(256, 2)
void gemm_mma_kernel(const float* __restrict__ bias)
{
    extern __shared__ char smem[];
    const uint32_t sbase = smem_u32(smem);
    const int tid = threadIdx.x;
    const int wid = tid >> 5;
    const int lane = tid & 31;
    const int warpM = wid & 3;
    const int warpN = wid >> 2;
    const int mblk = blockIdx.y;
    const int chblk = blockIdx.x;
    const int mBase = mblk * 128;
    const int chBase = chblk * 64;

    if (tid == 0) {
#pragma unroll
        for (int s = 0; s < 3; ++s) mbar_init(sbase + MBAR_OFF + s * 8, 1);
    }
    __syncthreads();

    auto issue = [&](int i, int s) {
        if (tid == 0) {
            const int kc = i & 3;
            const uint32_t mb = sbase + MBAR_OFF + s * 8;
            mbar_expect_tx(mb, STAGE_BYTES);
            bulk_g2s(sbase + s * STAGE_BYTES,
                     g_xh + (size_t)(mblk * 4 + kc) * 8192, 16384, mb);
            bulk_g2s(sbase + s * STAGE_BYTES + 16384,
                     g_wh + (size_t)(chblk * 4 + kc) * 8192, 16384, mb);
        }
    };

    // Prefetch chunks 0,1,2 into stages 0,1,2
    issue(0, 0);
    issue(1, 1);
    issue(2, 2);

    float acc[2][8][4];
#pragma unroll
    for (int mt = 0; mt < 2; ++mt)
#pragma unroll
        for (int nt = 0; nt < 8; ++nt)
#pragma unroll
            for (int e = 0; e < 4; ++e) acc[mt][nt][e] = 0.f;

    const int lrow = lane & 15;
    const int lkg = lane >> 4;

    auto compute_chunk = [&](uint32_t sA) {
        const uint32_t sB = sA + 16384;
#pragma unroll
        for (int ks = 0; ks < 4; ++ks) {
            uint32_t a[2][4];
#pragma unroll
            for (int mt = 0; mt < 2; ++mt) {
                uint32_t off = (warpM * 32 + mt * 16 + lrow) * 128 + ks * 32 + lkg * 16;
                ldsm4(a[mt][0], a[mt][1], a[mt][2], a[mt][3], sA + SW128(off));
            }
            uint32_t bf[4][4];
#pragma unroll
            for (int ng = 0; ng < 4; ++ng) {
                uint32_t off = (warpN * 64 + ng * 16 + lrow) * 128 + ks * 32 + lkg * 16;
                ldsm4(bf[ng][0], bf[ng][1], bf[ng][2], bf[ng][3], sB + SW128(off));
            }
#pragma unroll
            for (int mt = 0; mt < 2; ++mt)
#pragma unroll
                for (int ng = 0; ng < 4; ++ng) {
                    mma16816(acc[mt][2 * ng],     a[mt], bf[ng][0], bf[ng][2]);
                    mma16816(acc[mt][2 * ng + 1], a[mt], bf[ng][1], bf[ng][3]);
                }
        }
    };

    // Chunk 0 (stage 0, phase 0)
    mbar_wait(sbase + MBAR_OFF + 0, 0);
    compute_chunk(sbase);
    __syncthreads();                 // all warps drained stage 0
    issue(3, 0);                     // refill stage 0 with chunk 3

    // Chunks 1, 2 (stages 1, 2, phase 0) — no block syncs
    mbar_wait(sbase + MBAR_OFF + 8, 0);
    compute_chunk(sbase + STAGE_BYTES);
    mbar_wait(sbase + MBAR_OFF + 16, 0);
    compute_chunk(sbase + 2 * STAGE_BYTES);

    // Chunk 3 (stage 0, phase 1)
    mbar_wait(sbase + MBAR_OFF + 0, 1);
    compute_chunk(sbase);

    __syncthreads();   // all warps done with stage smem -> reuse for c/v tile

    // Predicate-light epilogue: gate math -> packed (c, v) half2 in smem.
    // e = exp(-gate) is range-safe (overflow -> inf -> rcp -> 0 = correct
    // limit), so z = rcp(1+e), c = e*z with NO sign predicates.
    __half2* cv_sm = (__half2*)smem;       // [128][CVP]
    const int qrow = lane >> 2;
    const int qch = lane & 3;

#pragma unroll
    for (int nt = 0; nt < 8; ++nt) {
        const int chL = warpN * 32 + nt * 4 + qch;
        const float bg = __ldg(bias + chBase + chL);
        const float bh = __ldg(bias + 256 + chBase + chL);
#pragma unroll
        for (int mt = 0; mt < 2; ++mt) {
#pragma unroll
            for (int half = 0; half < 2; ++half) {
                const int r = warpM * 32 + mt * 16 + half * 8 + qrow;
                const float gate = acc[mt][nt][2 * half] + bg;
                const float hid  = acc[mt][nt][2 * half + 1] + bh;

                const float e1 = __expf(-gate);
                const float z = frcp(1.f + e1);   // sigma(gate)
                const float c = e1 * z;           // sigma(-gate)

                const float e2 = __expf(-hid);
                const float sg = frcp(1.f + e2);  // sigma(hid)
                const float gv = (hid >= 0.f) ? (hid + 0.5f) : sg;

                cv_sm[r * CVP + chL] = __floats2half2_rn(c, z * gv);
            }
        }
    }
    __syncthreads();

    // Vectorized global stores of packed c/v (2 half2 = 8 bytes per op)
    for (int idx = tid; idx < 128 * 32; idx += 256) {
        int r = idx >> 5, cp = idx & 31;      // cp = channel pair
        *(uint2*)(g_cv + (size_t)(mBase + r) * HH + chBase + cp * 2) =
            *(uint2*)(cv_sm + r * CVP + cp * 2);
    }

    // Fused scan aggregates using ALL 256 threads: quarter-chunks of 32 rows,
    // then pairwise combine. From the ROUNDED fp16 values (coherent with apply).
    float* pA = (float*)(smem + PART_OFF);    // [4][64]
    float* pB = pA + 256;
    {
        const int ch = tid & 63;
        const int g = tid >> 6;               // 0..3: hp = g>>1, q = g&1
        float A = 1.f, Bv = 0.f;
        const int r0 = (g >> 1) * 64 + (g & 1) * 32;
#pragma unroll 8
        for (int r = 0; r < 32; ++r) {
            float2 cv = __half22float2(cv_sm[(r0 + r) * CVP + ch]);
            Bv = fmaf(cv.x, Bv, cv.y);
            A *= cv.x;
        }
        pA[g * 64 + ch] = A;
        pB[g * 64 + ch] = Bv;
    }
    __syncthreads();
    if (tid < 128) {
        const int ch = tid & 63;
        const int hp = tid >> 6;
        const float A0 = pA[(hp * 2) * 64 + ch];
        const float B0 = pB[(hp * 2) * 64 + ch];
        const float A1 = pA[(hp * 2 + 1) * 64 + ch];
        const float B1 = pB[(hp * 2 + 1) * 64 + ch];
        const float A = A1 * A0;
        const float Bv = fmaf(A1, B0, B1);
        const int gchunk = blockIdx.y * 2 + hp;
        const int b = gchunk >> 7;
        const int lc = gchunk & 127;
        const int h = chBase + ch;
        size_t gi = ((size_t)b * HH + h) * CC2 + lc;
        g_At[gi] = A;
        g_Bt[gi] = Bv;
    }
}

// ---------------------------------------------------------------------------
// Kernel 2: warp-parallel combine. One warp per (b,h) chain of 128 chunks.
// ---------------------------------------------------------------------------
__global__ __launch_bounds__(256)
void scan_combine_kernel(const float* __restrict__ h0)
{
    const int wid = threadIdx.x >> 5;
    const int lane = threadIdx.x & 31;
    const int chain = blockIdx.x * 8 + wid;       // 0..2047
    const int b = chain >> 8;
    const int h = chain & 255;

    const size_t base = ((size_t)b * HH + h) * CC2 + lane * 4;
    float4 A4 = *(const float4*)(g_At + base);
    float4 B4 = *(const float4*)(g_Bt + base);

    float a = A4.x, bb = B4.x;
    a = A4.y * a;  bb = fmaf(A4.y, bb, B4.y);
    a = A4.z * a;  bb = fmaf(A4.z, bb, B4.z);
    a = A4.w * a;  bb = fmaf(A4.w, bb, B4.w);

    float sa = a, sb = bb;
#pragma unroll
    for (int d = 1; d < 32; d <<= 1) {
        float pa = __shfl_up_sync(0xFFFFFFFFu, sa, d);
        float pb = __shfl_up_sync(0xFFFFFFFFu, sb, d);
        if (lane >= d) {
            sb = fmaf(sa, pb, sb);
            sa = sa * pa;
        }
    }
    float ea = __shfl_up_sync(0xFFFFFFFFu, sa, 1);
    float eb = __shfl_up_sync(0xFFFFFFFFu, sb, 1);
    if (lane == 0) { ea = 1.f; eb = 0.f; }

    float P = fmaf(ea, h0[b * HH + h], eb);

    const int c0 = lane * 4;
    size_t pi = ((size_t)b * CC2 + c0) * HH + h;
    g_P[pi] = P;             P = fmaf(A4.x, P, B4.x);
    g_P[pi + HH] = P;        P = fmaf(A4.y, P, B4.y);
    g_P[pi + 2 * HH] = P;    P = fmaf(A4.z, P, B4.z);
    g_P[pi + 3 * HH] = P;
}

// ---------------------------------------------------------------------------
// Kernel 3: apply carry-in over 64-step half-chunks, write outputs + h_next
// ---------------------------------------------------------------------------
__global__ __launch_bounds__(256)
void scan_apply_kernel(float* __restrict__ out, int out_size)
{
    const int bk = blockIdx.x;
    const int h = threadIdx.x;
    const int b = bk / CC2;
    const int chunk = bk % CC2;
    float hc = g_P[bk * HH + h];
    const size_t base = (size_t)bk * LC2 * HH + h;
#pragma unroll 8
    for (int t = 0; t < LC2; ++t) {
        float2 cv = __half22float2(g_cv[base + (size_t)t * HH]);
        hc = fmaf(cv.x, hc, cv.y);
        out[base + (size_t)t * HH] = hc;
    }
    if (chunk == CC2 - 1) {
        const long long off = (long long)MT * HH + b * HH + h;
        if (off < (long long)out_size) out[off] = hc;
    }
}

// ---------------------------------------------------------------------------
extern "C" void kernel_launch(void* const* d_in, const int* in_sizes, int n_in,
                              void* d_out, int out_size)
{
    const float* x  = (const float*)d_in[0];   // (B, S, IN)
    const float* h0 = (const float*)d_in[1];   // (B, 1, H)
    const float* W  = (const float*)d_in[2];   // (2H, IN)
    const float* b  = (const float*)d_in[3];   // (2H,)
    float* out = (float*)d_out;

    cudaFuncSetAttribute(gemm_mma_kernel,
                         cudaFuncAttributeMaxDynamicSharedMemorySize, SMEM_TOTAL_GEMM);

    slot_kernel<<<1, 32>>>();                  // launch-slot shim (see Kernel D)
    split_x_kernel<<<1024, 256>>>(x);
    split_w_kernel<<<64, 256>>>(W);

    dim3 ggrid(4, 512);
    gemm_mma_kernel<<<ggrid, 256, SMEM_TOTAL_GEMM>>>(b);
    scan_combine_kernel<<<256, 256>>>(h0);
    scan_apply_kernel<<<BB * CC2, 256>>>(out, out_size);
}